// round 1
// baseline (speedup 1.0000x reference)
#include <cuda_runtime.h>

#define BB  8
#define TT  1000
#define NHH 8
#define DD  64

// -(1/sqrt(64)) * log2(e)
#define SCALE_LOG2E (-0.18033688011112042f)

// Scratch (no allocs allowed): q, v, and per-head attention outputs, [b,h,t,d]
__device__ float g_q [BB*NHH*TT*DD];
__device__ float g_v [BB*NHH*TT*DD];
__device__ float g_ho[BB*NHH*TT*DD];

// ---------------------------------------------------------------------------
// K1: fused Q/V projection. C[m,n] = x[m,:] . w[n,:64] + w[n,64]
// m = b*T + t (8000), n = h*64 + d (512). Tile 64x64, K=64 in one shot.
// blockIdx.z selects (wq -> g_q) vs (wv -> g_v).
// ---------------------------------------------------------------------------
__global__ __launch_bounds__(256) void qv_kernel(
    const float* __restrict__ x, const float* __restrict__ wq,
    const float* __restrict__ wv) {
  const float* w  = blockIdx.z ? wv : wq;
  float*      dst = blockIdx.z ? g_v : g_q;
  const int m0 = blockIdx.x * 64;
  const int n0 = blockIdx.y * 64;

  __shared__ float xs[64*68];  // [k][m], stride 68
  __shared__ float ws[64*68];  // [k][n], stride 68
  const int tid = threadIdx.x;

  for (int i = tid; i < 64*16; i += 256) {
    int m = i >> 4, k4 = (i & 15) << 2;
    float4 v4 = *(const float4*)&x[(m0 + m)*DD + k4];
    xs[(k4+0)*68 + m] = v4.x;
    xs[(k4+1)*68 + m] = v4.y;
    xs[(k4+2)*68 + m] = v4.z;
    xs[(k4+3)*68 + m] = v4.w;
  }
  for (int i = tid; i < 64*64; i += 256) {
    int n = i >> 6, k = i & 63;
    ws[k*68 + n] = w[(n0 + n)*65 + k];
  }
  __syncthreads();

  const int tm = (tid >> 4) * 4;  // 4 m-rows
  const int tn = (tid & 15) * 4;  // 4 n-cols (consecutive d within one head)
  float acc[4][4];
  #pragma unroll
  for (int i = 0; i < 4; i++)
    #pragma unroll
    for (int j = 0; j < 4; j++) acc[i][j] = 0.f;

  #pragma unroll 8
  for (int k = 0; k < 64; k++) {
    float4 a4 = *(const float4*)&xs[k*68 + tm];
    float4 b4 = *(const float4*)&ws[k*68 + tn];
    float av[4] = {a4.x, a4.y, a4.z, a4.w};
    float bv[4] = {b4.x, b4.y, b4.z, b4.w};
    #pragma unroll
    for (int i = 0; i < 4; i++)
      #pragma unroll
      for (int j = 0; j < 4; j++) acc[i][j] += av[i] * bv[j];
  }

  const int n = n0 + tn;
  const int h = n >> 6, d0 = n & 63;
  float b0 = w[(n+0)*65 + 64];
  float b1 = w[(n+1)*65 + 64];
  float b2 = w[(n+2)*65 + 64];
  float b3 = w[(n+3)*65 + 64];
  #pragma unroll
  for (int i = 0; i < 4; i++) {
    int m = m0 + tm + i;
    int b = m / TT, t = m - b*TT;
    float4 o;
    o.x = acc[i][0] + b0;
    o.y = acc[i][1] + b1;
    o.z = acc[i][2] + b2;
    o.w = acc[i][3] + b3;
    *(float4*)&dst[((b*NHH + h)*TT + t)*DD + d0] = o;
  }
}

// ---------------------------------------------------------------------------
// K2: L1-distance attention for one (b, h, 64-query tile).
// scores <= 0 and the null-source logit is 0, so softmax max == 0 exactly:
//   p = exp(score), denom = 1 + sum_s p. No online rescaling needed.
// 128 threads. Score micro-tile 4t x 8s; AV micro-tile 4t x 8w.
// ---------------------------------------------------------------------------
__global__ __launch_bounds__(128, 3) void attn_kernel(
    const float* __restrict__ x, const float* __restrict__ wk) {
  extern __shared__ float sm[];
  float* qs    = sm;             // [d][t] stride 68 (transposed)
  float* ks    = sm + 4352;      // [d][s] stride 68 (transposed)
  float* vs    = sm + 2*4352;    // [s][w] stride 68
  float* ps    = sm + 3*4352;    // [s][t] stride 68 (transposed)
  float* wks   = sm + 4*4352;    // [64]
  float* denom = wks + 64;       // [64]

  const int b  = blockIdx.z;
  const int h  = blockIdx.y;
  const int t0 = blockIdx.x * 64;
  const int tid = threadIdx.x;
  const int tt = (tid & 15) * 4;  // this thread's 4 query rows
  const int g8 = (tid >> 4) * 8;  // 8 sources (score phase) / 8 dims (AV phase)

  if (tid < 64) { wks[tid] = wk[h*DD + tid]; denom[tid] = 0.f; }

  const float* qg = g_q + (size_t)(b*NHH + h)*TT*DD;
  const float* vg = g_v + (size_t)(b*NHH + h)*TT*DD;
  const float* xg = x   + (size_t)b*TT*DD;

  // load q tile transposed
  for (int i = tid; i < 64*16; i += 128) {
    int t = i >> 4, k4 = (i & 15) << 2;
    int trow = t0 + t; if (trow >= TT) trow = TT - 1;  // clamp, result unused
    float4 v4 = *(const float4*)&qg[trow*DD + k4];
    qs[(k4+0)*68 + t] = v4.x;
    qs[(k4+1)*68 + t] = v4.y;
    qs[(k4+2)*68 + t] = v4.z;
    qs[(k4+3)*68 + t] = v4.w;
  }
  __syncthreads();

  float oacc[4][8];
  #pragma unroll
  for (int i = 0; i < 4; i++)
    #pragma unroll
    for (int j = 0; j < 8; j++) oacc[i][j] = 0.f;

  for (int s0 = 0; s0 < TT; s0 += 64) {
    // load k = x * wk[h] (transposed) and v chunk
    for (int i = tid; i < 64*16; i += 128) {
      int s = i >> 4, k4 = (i & 15) << 2;
      int srow = s0 + s;
      float4 xv = make_float4(0.f,0.f,0.f,0.f);
      float4 vv = make_float4(0.f,0.f,0.f,0.f);
      if (srow < TT) {
        xv = *(const float4*)&xg[srow*DD + k4];
        vv = *(const float4*)&vg[srow*DD + k4];
      }
      ks[(k4+0)*68 + s] = xv.x * wks[k4+0];
      ks[(k4+1)*68 + s] = xv.y * wks[k4+1];
      ks[(k4+2)*68 + s] = xv.z * wks[k4+2];
      ks[(k4+3)*68 + s] = xv.w * wks[k4+3];
      *(float4*)&vs[s*68 + k4] = vv;
    }
    __syncthreads();

    // L1-distance scores
    float sacc[4][8];
    #pragma unroll
    for (int i = 0; i < 4; i++)
      #pragma unroll
      for (int j = 0; j < 8; j++) sacc[i][j] = 0.f;

    const float* qp = qs + tt;
    const float* kp = ks + g8;
    #pragma unroll 4
    for (int d = 0; d < 64; d++) {
      float4 q4 = *(const float4*)(qp + d*68);
      float4 ka = *(const float4*)(kp + d*68);
      float4 kb = *(const float4*)(kp + d*68 + 4);
      float qv[4] = {q4.x, q4.y, q4.z, q4.w};
      float kv[8] = {ka.x, ka.y, ka.z, ka.w, kb.x, kb.y, kb.z, kb.w};
      #pragma unroll
      for (int i = 0; i < 4; i++)
        #pragma unroll
        for (int j = 0; j < 8; j++)
          sacc[i][j] += fabsf(qv[i] - kv[j]);
    }

    // p = exp2(-scale*log2e * sum|q-k|), masked past T; write transposed [s][t]
    #pragma unroll
    for (int j = 0; j < 8; j++) {
      int srow = s0 + g8 + j;
      float e0, e1, e2, e3;
      asm("ex2.approx.f32 %0, %1;" : "=f"(e0) : "f"(sacc[0][j] * SCALE_LOG2E));
      asm("ex2.approx.f32 %0, %1;" : "=f"(e1) : "f"(sacc[1][j] * SCALE_LOG2E));
      asm("ex2.approx.f32 %0, %1;" : "=f"(e2) : "f"(sacc[2][j] * SCALE_LOG2E));
      asm("ex2.approx.f32 %0, %1;" : "=f"(e3) : "f"(sacc[3][j] * SCALE_LOG2E));
      if (srow >= TT) { e0 = e1 = e2 = e3 = 0.f; }
      float4 pv; pv.x = e0; pv.y = e1; pv.z = e2; pv.w = e3;
      *(float4*)&ps[(g8+j)*68 + tt] = pv;
    }
    __syncthreads();

    // denominator partial sums (warps 0-1 only; uniform per warp)
    if (tid < 64) {
      float dsum = 0.f;
      #pragma unroll 8
      for (int s = 0; s < 64; s++) dsum += ps[s*68 + tid];
      denom[tid] += dsum;
    }

    // AV accumulation: oacc[t][w] += sum_s p[s][t] * v[s][w]
    const float* pp = ps + tt;
    const float* vp = vs + g8;
    #pragma unroll 4
    for (int s = 0; s < 64; s++) {
      float4 p4 = *(const float4*)(pp + s*68);
      float4 va = *(const float4*)(vp + s*68);
      float4 vb = *(const float4*)(vp + s*68 + 4);
      float pv_[4] = {p4.x, p4.y, p4.z, p4.w};
      float vv_[8] = {va.x, va.y, va.z, va.w, vb.x, vb.y, vb.z, vb.w};
      #pragma unroll
      for (int i = 0; i < 4; i++)
        #pragma unroll
        for (int j = 0; j < 8; j++)
          oacc[i][j] += pv_[i] * vv_[j];
    }
    __syncthreads();
  }

  // normalize by (1 + sum p) and store per-head output
  float* hop = g_ho + (size_t)(b*NHH + h)*TT*DD;
  #pragma unroll
  for (int i = 0; i < 4; i++) {
    int trow = t0 + tt + i;
    if (trow < TT) {
      float inv = 1.f / (1.f + denom[tt + i]);
      float4 o1, o2;
      o1.x = oacc[i][0]*inv; o1.y = oacc[i][1]*inv;
      o1.z = oacc[i][2]*inv; o1.w = oacc[i][3]*inv;
      o2.x = oacc[i][4]*inv; o2.y = oacc[i][5]*inv;
      o2.z = oacc[i][6]*inv; o2.w = oacc[i][7]*inv;
      *(float4*)&hop[trow*DD + g8]     = o1;
      *(float4*)&hop[trow*DD + g8 + 4] = o2;
    }
  }
}

// ---------------------------------------------------------------------------
// K3: sum over heads, ReLU, y = Wf . r + bias, out = x + y.
// 4 tokens per block, 64 threads per token.
// ---------------------------------------------------------------------------
__global__ __launch_bounds__(256) void out_kernel(
    const float* __restrict__ x, const float* __restrict__ wf,
    float* __restrict__ out) {
  __shared__ float r[4][64];
  __shared__ float wfs[64*65];
  const int tl = threadIdx.x >> 6;
  const int w  = threadIdx.x & 63;
  const int token = blockIdx.x*4 + tl;
  const int b = token / TT, t = token - b*TT;

  for (int i = threadIdx.x; i < 64*65; i += 256) wfs[i] = wf[i];

  float s = 0.f;
  #pragma unroll
  for (int h = 0; h < NHH; h++)
    s += g_ho[((size_t)(b*NHH + h)*TT + t)*DD + w];
  r[tl][w] = fmaxf(s, 0.f);
  __syncthreads();

  float acc = wfs[w*65 + 64];
  #pragma unroll 8
  for (int k = 0; k < 64; k++)
    acc += wfs[w*65 + k] * r[tl][k];

  out[(size_t)token*DD + w] = x[(size_t)token*DD + w] + acc;
}

// ---------------------------------------------------------------------------
extern "C" void kernel_launch(void* const* d_in, const int* in_sizes, int n_in,
                              void* d_out, int out_size) {
  const float* x  = (const float*)d_in[0];  // [8,1000,64]
  const float* wq = (const float*)d_in[1];  // [512,65]
  const float* wv = (const float*)d_in[2];  // [512,65]
  const float* wk = (const float*)d_in[3];  // [8,64]
  const float* wf = (const float*)d_in[4];  // [64,65]
  float* out = (float*)d_out;               // [8,1000,64]

  (void)in_sizes; (void)n_in; (void)out_size;

  const int ATTN_SMEM = (4*4352 + 128) * 4;  // 70144 B
  cudaFuncSetAttribute(attn_kernel, cudaFuncAttributeMaxDynamicSharedMemorySize,
                       ATTN_SMEM);

  qv_kernel<<<dim3(8000/64, 512/64, 2), 256>>>(x, wq, wv);
  attn_kernel<<<dim3(16, NHH, BB), 128, ATTN_SMEM>>>(x, wk);
  out_kernel<<<8000/4, 256>>>(x, wf, out);
}

// round 3
// speedup vs baseline: 1.2170x; 1.2170x over previous
#include <cuda_runtime.h>
#include <cuda_fp16.h>

#define BB  8
#define TT  1000
#define NHH 8
#define DD  64

// -(1/sqrt(64)) * log2(e)
#define SCALE_LOG2E (-0.18033688011112042f)

// Scratch (no allocs allowed): q, v, and per-head attention outputs, [b,h,t,d]
__device__ float g_q [BB*NHH*TT*DD];
__device__ float g_v [BB*NHH*TT*DD];
__device__ float g_ho[BB*NHH*TT*DD];

__device__ __forceinline__ __half2 habs2_(__half2 a) {
  unsigned u = (*(unsigned*)&a) & 0x7FFF7FFFu;   // LOP3 on alu pipe
  return *(__half2*)&u;
}

// ---------------------------------------------------------------------------
// K1: fused Q/V projection. C[m,n] = x[m,:] . w[n,:64] + w[n,64]
// ---------------------------------------------------------------------------
__global__ __launch_bounds__(256) void qv_kernel(
    const float* __restrict__ x, const float* __restrict__ wq,
    const float* __restrict__ wv) {
  const float* w  = blockIdx.z ? wv : wq;
  float*      dst = blockIdx.z ? g_v : g_q;
  const int m0 = blockIdx.x * 64;
  const int n0 = blockIdx.y * 64;

  __shared__ float xs[64*68];  // [k][m], stride 68
  __shared__ float ws[64*68];  // [k][n], stride 68
  const int tid = threadIdx.x;

  for (int i = tid; i < 64*16; i += 256) {
    int m = i >> 4, k4 = (i & 15) << 2;
    float4 v4 = *(const float4*)&x[(m0 + m)*DD + k4];
    xs[(k4+0)*68 + m] = v4.x;
    xs[(k4+1)*68 + m] = v4.y;
    xs[(k4+2)*68 + m] = v4.z;
    xs[(k4+3)*68 + m] = v4.w;
  }
  for (int i = tid; i < 64*64; i += 256) {
    int n = i >> 6, k = i & 63;
    ws[k*68 + n] = w[(n0 + n)*65 + k];
  }
  __syncthreads();

  const int tm = (tid >> 4) * 4;
  const int tn = (tid & 15) * 4;
  float acc[4][4];
  #pragma unroll
  for (int i = 0; i < 4; i++)
    #pragma unroll
    for (int j = 0; j < 4; j++) acc[i][j] = 0.f;

  #pragma unroll 8
  for (int k = 0; k < 64; k++) {
    float4 a4 = *(const float4*)&xs[k*68 + tm];
    float4 b4 = *(const float4*)&ws[k*68 + tn];
    float av[4] = {a4.x, a4.y, a4.z, a4.w};
    float bv[4] = {b4.x, b4.y, b4.z, b4.w};
    #pragma unroll
    for (int i = 0; i < 4; i++)
      #pragma unroll
      for (int j = 0; j < 4; j++) acc[i][j] += av[i] * bv[j];
  }

  const int n = n0 + tn;
  const int h = n >> 6, d0 = n & 63;
  float b0 = w[(n+0)*65 + 64];
  float b1 = w[(n+1)*65 + 64];
  float b2 = w[(n+2)*65 + 64];
  float b3 = w[(n+3)*65 + 64];
  #pragma unroll
  for (int i = 0; i < 4; i++) {
    int m = m0 + tm + i;
    int b = m / TT, t = m - b*TT;
    float4 o;
    o.x = acc[i][0] + b0;
    o.y = acc[i][1] + b1;
    o.z = acc[i][2] + b2;
    o.w = acc[i][3] + b3;
    *(float4*)&dst[((b*NHH + h)*TT + t)*DD + d0] = o;
  }
}

// ---------------------------------------------------------------------------
// K2: L1-distance attention. Score loop in fp16x2 (2 sources per half2 lane),
// accumulated in 16-d chunks then drained to fp32. AV stays fp32 FFMA.
// softmax max == 0 exactly (scores <= 0, null logit = 0): p=exp(s),
// denom = 1 + sum p.
// ---------------------------------------------------------------------------
// SMEM layout (bytes):
//   qsh : half [64][72]          9216
//   ksh : half2 [64][36]         9216   (pair of sources per half2)
//   vs  : float [64][68]        17408
//   ps  : float [64][68]        17408
//   wks : float [64], denom: float[64]   512
#define SM_QSH   0
#define SM_KSH   9216
#define SM_VS    18432
#define SM_PS    (18432 + 17408)
#define SM_WKS   (18432 + 2*17408)
#define ATTN_SMEM (SM_WKS + 512)

__global__ __launch_bounds__(128, 3) void attn_kernel(
    const float* __restrict__ x, const float* __restrict__ wk) {
  extern __shared__ char smraw[];
  __half*  qsh   = (__half*)(smraw + SM_QSH);
  __half2* ksh   = (__half2*)(smraw + SM_KSH);
  float*   vs    = (float*)(smraw + SM_VS);
  float*   ps    = (float*)(smraw + SM_PS);
  float*   wks   = (float*)(smraw + SM_WKS);
  float*   denom = wks + 64;

  const int b  = blockIdx.z;
  const int h  = blockIdx.y;
  const int t0 = blockIdx.x * 64;
  const int tid = threadIdx.x;
  const int tt  = (tid & 15) * 4;  // 4 query rows
  const int g8  = (tid >> 4) * 8;  // 8 sources (score) / 8 dims (AV)
  const int sp0 = g8 >> 1;         // 4 half2 source-pairs

  if (tid < 64) { wks[tid] = wk[h*DD + tid]; denom[tid] = 0.f; }
  __syncthreads();   // wks needed by k loader below

  const float* qg = g_q + (size_t)(b*NHH + h)*TT*DD;
  const float* vg = g_v + (size_t)(b*NHH + h)*TT*DD;
  const float* xg = x   + (size_t)b*TT*DD;

  // load q tile -> fp16, transposed [d][t]
  for (int i = tid; i < 64*16; i += 128) {
    int t = i >> 4, k4 = (i & 15) << 2;
    int trow = t0 + t; if (trow >= TT) trow = TT - 1;  // clamp; result unused
    float4 v4 = *(const float4*)&qg[trow*DD + k4];
    qsh[(k4+0)*72 + t] = __float2half_rn(v4.x);
    qsh[(k4+1)*72 + t] = __float2half_rn(v4.y);
    qsh[(k4+2)*72 + t] = __float2half_rn(v4.z);
    qsh[(k4+3)*72 + t] = __float2half_rn(v4.w);
  }
  __syncthreads();

  float oacc[4][8];
  #pragma unroll
  for (int i = 0; i < 4; i++)
    #pragma unroll
    for (int j = 0; j < 8; j++) oacc[i][j] = 0.f;

  for (int s0 = 0; s0 < TT; s0 += 64) {
    // load k = x*wk (fp16 pairs, transposed [d][spair]) and v chunk (fp32)
    for (int i = tid; i < 512; i += 128) {
      int sp = i >> 4, k4 = (i & 15) << 2;
      int r0 = s0 + 2*sp, r1 = r0 + 1;
      float4 xa = make_float4(0.f,0.f,0.f,0.f);
      float4 xb = make_float4(0.f,0.f,0.f,0.f);
      float4 va = make_float4(0.f,0.f,0.f,0.f);
      float4 vb = make_float4(0.f,0.f,0.f,0.f);
      if (r0 < TT) { xa = *(const float4*)&xg[r0*DD + k4];
                     va = *(const float4*)&vg[r0*DD + k4]; }
      if (r1 < TT) { xb = *(const float4*)&xg[r1*DD + k4];
                     vb = *(const float4*)&vg[r1*DD + k4]; }
      float w0 = wks[k4+0], w1 = wks[k4+1], w2 = wks[k4+2], w3 = wks[k4+3];
      ksh[(k4+0)*36 + sp] = __floats2half2_rn(xa.x*w0, xb.x*w0);
      ksh[(k4+1)*36 + sp] = __floats2half2_rn(xa.y*w1, xb.y*w1);
      ksh[(k4+2)*36 + sp] = __floats2half2_rn(xa.z*w2, xb.z*w2);
      ksh[(k4+3)*36 + sp] = __floats2half2_rn(xa.w*w3, xb.w*w3);
      *(float4*)&vs[(2*sp+0)*68 + k4] = va;
      *(float4*)&vs[(2*sp+1)*68 + k4] = vb;
    }
    __syncthreads();

    // ---- L1-distance scores, fp16x2, chunked fp32 drain ----
    float sacc[4][8];
    #pragma unroll
    for (int i = 0; i < 4; i++)
      #pragma unroll
      for (int j = 0; j < 8; j++) sacc[i][j] = 0.f;

    const __half*  qp = qsh + tt;
    const __half2* kp = ksh + sp0;

    #pragma unroll
    for (int dc = 0; dc < 4; dc++) {
      __half2 sc2[4][4];
      #pragma unroll
      for (int i = 0; i < 4; i++)
        #pragma unroll
        for (int jp = 0; jp < 4; jp++) sc2[i][jp] = __float2half2_rn(0.f);

      #pragma unroll 4
      for (int dd = 0; dd < 16; dd++) {
        int d = dc*16 + dd;
        // 4 query halfs (LDS.64) -> broadcast half2
        __half2 qraw[2];
        *(uint2*)qraw = *(const uint2*)(qp + d*72);
        __half2 qq[4];
        qq[0] = __half2half2(__low2half (qraw[0]));
        qq[1] = __half2half2(__high2half(qraw[0]));
        qq[2] = __half2half2(__low2half (qraw[1]));
        qq[3] = __half2half2(__high2half(qraw[1]));
        // 4 source-pair half2 (LDS.128)
        __half2 kk[4];
        *(uint4*)kk = *(const uint4*)(kp + d*36);
        #pragma unroll
        for (int i = 0; i < 4; i++)
          #pragma unroll
          for (int jp = 0; jp < 4; jp++)
            sc2[i][jp] = __hadd2(sc2[i][jp], habs2_(__hsub2(qq[i], kk[jp])));
      }
      // drain to fp32
      #pragma unroll
      for (int i = 0; i < 4; i++)
        #pragma unroll
        for (int jp = 0; jp < 4; jp++) {
          float2 f = __half22float2(sc2[i][jp]);
          sacc[i][2*jp+0] += f.x;
          sacc[i][2*jp+1] += f.y;
        }
    }

    // p = exp2(SCALE_LOG2E * sum), masked past T; write transposed [s][t]
    #pragma unroll
    for (int j = 0; j < 8; j++) {
      int srow = s0 + g8 + j;
      float e0, e1, e2, e3;
      asm("ex2.approx.f32 %0, %1;" : "=f"(e0) : "f"(sacc[0][j] * SCALE_LOG2E));
      asm("ex2.approx.f32 %0, %1;" : "=f"(e1) : "f"(sacc[1][j] * SCALE_LOG2E));
      asm("ex2.approx.f32 %0, %1;" : "=f"(e2) : "f"(sacc[2][j] * SCALE_LOG2E));
      asm("ex2.approx.f32 %0, %1;" : "=f"(e3) : "f"(sacc[3][j] * SCALE_LOG2E));
      if (srow >= TT) { e0 = e1 = e2 = e3 = 0.f; }
      float4 pv; pv.x = e0; pv.y = e1; pv.z = e2; pv.w = e3;
      *(float4*)&ps[(g8+j)*68 + tt] = pv;
    }
    __syncthreads();

    // denominator partial sums (threads 0-63, one per query)
    if (tid < 64) {
      float dsum = 0.f;
      #pragma unroll 8
      for (int s = 0; s < 64; s++) dsum += ps[s*68 + tid];
      denom[tid] += dsum;
    }

    // AV: oacc[t][w] += sum_s p[s][t] * v[s][w]
    const float* pp = ps + tt;
    const float* vp = vs + g8;
    #pragma unroll 4
    for (int s = 0; s < 64; s++) {
      float4 p4 = *(const float4*)(pp + s*68);
      float4 va = *(const float4*)(vp + s*68);
      float4 vb = *(const float4*)(vp + s*68 + 4);
      float pv_[4] = {p4.x, p4.y, p4.z, p4.w};
      float vv_[8] = {va.x, va.y, va.z, va.w, vb.x, vb.y, vb.z, vb.w};
      #pragma unroll
      for (int i = 0; i < 4; i++)
        #pragma unroll
        for (int j = 0; j < 8; j++)
          oacc[i][j] += pv_[i] * vv_[j];
    }
    __syncthreads();
  }

  // normalize by (1 + sum p) and store per-head output
  float* hop = g_ho + (size_t)(b*NHH + h)*TT*DD;
  #pragma unroll
  for (int i = 0; i < 4; i++) {
    int trow = t0 + tt + i;
    if (trow < TT) {
      float inv = 1.f / (1.f + denom[tt + i]);
      float4 o1, o2;
      o1.x = oacc[i][0]*inv; o1.y = oacc[i][1]*inv;
      o1.z = oacc[i][2]*inv; o1.w = oacc[i][3]*inv;
      o2.x = oacc[i][4]*inv; o2.y = oacc[i][5]*inv;
      o2.z = oacc[i][6]*inv; o2.w = oacc[i][7]*inv;
      *(float4*)&hop[trow*DD + g8]     = o1;
      *(float4*)&hop[trow*DD + g8 + 4] = o2;
    }
  }
}

// ---------------------------------------------------------------------------
// K3: sum over heads, ReLU, y = Wf . r + bias, out = x + y.
// ---------------------------------------------------------------------------
__global__ __launch_bounds__(256) void out_kernel(
    const float* __restrict__ x, const float* __restrict__ wf,
    float* __restrict__ out) {
  __shared__ float r[4][64];
  __shared__ float wfs[64*65];
  const int tl = threadIdx.x >> 6;
  const int w  = threadIdx.x & 63;
  const int token = blockIdx.x*4 + tl;
  const int b = token / TT, t = token - b*TT;

  for (int i = threadIdx.x; i < 64*65; i += 256) wfs[i] = wf[i];

  float s = 0.f;
  #pragma unroll
  for (int h = 0; h < NHH; h++)
    s += g_ho[((size_t)(b*NHH + h)*TT + t)*DD + w];
  r[tl][w] = fmaxf(s, 0.f);
  __syncthreads();

  float acc = wfs[w*65 + 64];
  #pragma unroll 8
  for (int k = 0; k < 64; k++)
    acc += wfs[w*65 + k] * r[tl][k];

  out[(size_t)token*DD + w] = x[(size_t)token*DD + w] + acc;
}

// ---------------------------------------------------------------------------
extern "C" void kernel_launch(void* const* d_in, const int* in_sizes, int n_in,
                              void* d_out, int out_size) {
  const float* x  = (const float*)d_in[0];  // [8,1000,64]
  const float* wq = (const float*)d_in[1];  // [512,65]
  const float* wv = (const float*)d_in[2];  // [512,65]
  const float* wk = (const float*)d_in[3];  // [8,64]
  const float* wf = (const float*)d_in[4];  // [64,65]
  float* out = (float*)d_out;               // [8,1000,64]

  (void)in_sizes; (void)n_in; (void)out_size;

  cudaFuncSetAttribute(attn_kernel, cudaFuncAttributeMaxDynamicSharedMemorySize,
                       ATTN_SMEM);

  qv_kernel<<<dim3(8000/64, 512/64, 2), 256>>>(x, wq, wv);
  attn_kernel<<<dim3(16, NHH, BB), 128, ATTN_SMEM>>>(x, wk);
  out_kernel<<<8000/4, 256>>>(x, wf, out);
}

// round 4
// speedup vs baseline: 1.2460x; 1.0238x over previous
#include <cuda_runtime.h>
#include <cuda_fp16.h>

#define BB  8
#define TT  1000
#define NHH 8
#define DD  64

// -(1/sqrt(64)) * log2(e)
#define SCALE_LOG2E (-0.18033688011112042f)

// Scratch (no allocs allowed): q, v, and per-head attention outputs, [b,h,t,d]
__device__ float g_q [BB*NHH*TT*DD];
__device__ float g_v [BB*NHH*TT*DD];
__device__ float g_ho[BB*NHH*TT*DD];

__device__ __forceinline__ __half2 habs2_(__half2 a) {
  unsigned u = (*(unsigned*)&a) & 0x7FFF7FFFu;   // LOP3 on alu pipe
  return *(__half2*)&u;
}

// ---------------------------------------------------------------------------
// K1: fused Q/V projection. C[m,n] = x[m,:] . w[n,:64] + w[n,64]
// ---------------------------------------------------------------------------
__global__ __launch_bounds__(256) void qv_kernel(
    const float* __restrict__ x, const float* __restrict__ wq,
    const float* __restrict__ wv) {
  const float* w  = blockIdx.z ? wv : wq;
  float*      dst = blockIdx.z ? g_v : g_q;
  const int m0 = blockIdx.x * 64;
  const int n0 = blockIdx.y * 64;

  __shared__ float xs[64*68];  // [k][m], stride 68
  __shared__ float ws[64*68];  // [k][n], stride 68
  const int tid = threadIdx.x;

  for (int i = tid; i < 64*16; i += 256) {
    int m = i >> 4, k4 = (i & 15) << 2;
    float4 v4 = *(const float4*)&x[(m0 + m)*DD + k4];
    xs[(k4+0)*68 + m] = v4.x;
    xs[(k4+1)*68 + m] = v4.y;
    xs[(k4+2)*68 + m] = v4.z;
    xs[(k4+3)*68 + m] = v4.w;
  }
  for (int i = tid; i < 64*64; i += 256) {
    int n = i >> 6, k = i & 63;
    ws[k*68 + n] = w[(n0 + n)*65 + k];
  }
  __syncthreads();

  const int tm = (tid >> 4) * 4;
  const int tn = (tid & 15) * 4;
  float acc[4][4];
  #pragma unroll
  for (int i = 0; i < 4; i++)
    #pragma unroll
    for (int j = 0; j < 4; j++) acc[i][j] = 0.f;

  #pragma unroll 8
  for (int k = 0; k < 64; k++) {
    float4 a4 = *(const float4*)&xs[k*68 + tm];
    float4 b4 = *(const float4*)&ws[k*68 + tn];
    float av[4] = {a4.x, a4.y, a4.z, a4.w};
    float bv[4] = {b4.x, b4.y, b4.z, b4.w};
    #pragma unroll
    for (int i = 0; i < 4; i++)
      #pragma unroll
      for (int j = 0; j < 4; j++) acc[i][j] += av[i] * bv[j];
  }

  const int n = n0 + tn;
  const int h = n >> 6, d0 = n & 63;
  float b0 = w[(n+0)*65 + 64];
  float b1 = w[(n+1)*65 + 64];
  float b2 = w[(n+2)*65 + 64];
  float b3 = w[(n+3)*65 + 64];
  #pragma unroll
  for (int i = 0; i < 4; i++) {
    int m = m0 + tm + i;
    int b = m / TT, t = m - b*TT;
    float4 o;
    o.x = acc[i][0] + b0;
    o.y = acc[i][1] + b1;
    o.z = acc[i][2] + b2;
    o.w = acc[i][3] + b3;
    *(float4*)&dst[((b*NHH + h)*TT + t)*DD + d0] = o;
  }
}

// ---------------------------------------------------------------------------
// K2: L1-distance attention, all-fp16x2 math.
//   scores: HSUB2/HADD2, 2 sources per lane, 16-d chunk drains to fp32
//   AV:     HFMA2, 2 value-dims per lane, 32-s chunk drains to fp32
//   q and p stored in smem PRE-DUPLICATED as half2 -> no broadcast PRMTs
//   denom via per-thread register sums + shared atomicAdd
// softmax max == 0 exactly (scores <= 0, null logit = 0).
// ---------------------------------------------------------------------------
// SMEM layout (bytes):
//   qsh2 : half2 [64 d][72 t]   (duplicated)   18432
//   ksh  : half2 [64 d][36 sp]  (source pairs)  9216
//   vsh  : half2 [64 s][36 wp]  (dim pairs)     9216
//   ps2  : half2 [64 s][68 t]   (duplicated)   17408
//   wks  : float [64]; denom : float [64]         512
#define SM_QSH2  0
#define SM_KSH   18432
#define SM_VSH   (18432 + 9216)
#define SM_PS2   (18432 + 2*9216)
#define SM_WKS   (SM_PS2 + 17408)
#define ATTN_SMEM (SM_WKS + 512)

__global__ __launch_bounds__(128, 3) void attn_kernel(
    const float* __restrict__ x, const float* __restrict__ wk) {
  extern __shared__ char smraw[];
  __half2* qsh2  = (__half2*)(smraw + SM_QSH2);
  __half2* ksh   = (__half2*)(smraw + SM_KSH);
  __half2* vsh   = (__half2*)(smraw + SM_VSH);
  __half2* ps2   = (__half2*)(smraw + SM_PS2);
  float*   wks   = (float*)(smraw + SM_WKS);
  float*   denom = wks + 64;

  const int b  = blockIdx.z;
  const int h  = blockIdx.y;
  const int t0 = blockIdx.x * 64;
  const int tid = threadIdx.x;
  const int tt  = (tid & 15) * 4;  // 4 query rows
  const int g8  = (tid >> 4) * 8;  // 8 sources (score) / 8 dims (AV)
  const int sp0 = g8 >> 1;         // 4 half2 pairs (sources or dims)

  if (tid < 64) { wks[tid] = wk[h*DD + tid]; denom[tid] = 0.f; }
  __syncthreads();   // wks needed by k loader; denom must be zeroed

  const float* qg = g_q + (size_t)(b*NHH + h)*TT*DD;
  const float* vg = g_v + (size_t)(b*NHH + h)*TT*DD;
  const float* xg = x   + (size_t)b*TT*DD;

  // load q tile -> duplicated half2, transposed [d][t]
  for (int i = tid; i < 64*16; i += 128) {
    int t = i >> 4, k4 = (i & 15) << 2;
    int trow = t0 + t; if (trow >= TT) trow = TT - 1;  // clamp; result unused
    float4 v4 = *(const float4*)&qg[trow*DD + k4];
    qsh2[(k4+0)*72 + t] = __floats2half2_rn(v4.x, v4.x);
    qsh2[(k4+1)*72 + t] = __floats2half2_rn(v4.y, v4.y);
    qsh2[(k4+2)*72 + t] = __floats2half2_rn(v4.z, v4.z);
    qsh2[(k4+3)*72 + t] = __floats2half2_rn(v4.w, v4.w);
  }
  __syncthreads();

  float oacc[4][8];
  #pragma unroll
  for (int i = 0; i < 4; i++)
    #pragma unroll
    for (int j = 0; j < 8; j++) oacc[i][j] = 0.f;

  for (int s0 = 0; s0 < TT; s0 += 64) {
    // load k = x*wk (half2 source pairs, [d][sp]) and v (half2 dim pairs, [s][wp])
    for (int i = tid; i < 512; i += 128) {
      int sp = i >> 4, k4 = (i & 15) << 2;
      int r0 = s0 + 2*sp, r1 = r0 + 1;
      float4 xa = make_float4(0.f,0.f,0.f,0.f);
      float4 xb = make_float4(0.f,0.f,0.f,0.f);
      float4 va = make_float4(0.f,0.f,0.f,0.f);
      float4 vb = make_float4(0.f,0.f,0.f,0.f);
      if (r0 < TT) { xa = *(const float4*)&xg[r0*DD + k4];
                     va = *(const float4*)&vg[r0*DD + k4]; }
      if (r1 < TT) { xb = *(const float4*)&xg[r1*DD + k4];
                     vb = *(const float4*)&vg[r1*DD + k4]; }
      float w0 = wks[k4+0], w1 = wks[k4+1], w2 = wks[k4+2], w3 = wks[k4+3];
      ksh[(k4+0)*36 + sp] = __floats2half2_rn(xa.x*w0, xb.x*w0);
      ksh[(k4+1)*36 + sp] = __floats2half2_rn(xa.y*w1, xb.y*w1);
      ksh[(k4+2)*36 + sp] = __floats2half2_rn(xa.z*w2, xb.z*w2);
      ksh[(k4+3)*36 + sp] = __floats2half2_rn(xa.w*w3, xb.w*w3);
      // v rows 2*sp and 2*sp+1, dims k4..k4+3 -> half2 pairs
      vsh[(2*sp+0)*36 + (k4>>1)]     = __floats2half2_rn(va.x, va.y);
      vsh[(2*sp+0)*36 + (k4>>1) + 1] = __floats2half2_rn(va.z, va.w);
      vsh[(2*sp+1)*36 + (k4>>1)]     = __floats2half2_rn(vb.x, vb.y);
      vsh[(2*sp+1)*36 + (k4>>1) + 1] = __floats2half2_rn(vb.z, vb.w);
    }
    __syncthreads();

    // ---- L1-distance scores, fp16x2, chunked fp32 drain ----
    float sacc[4][8];
    #pragma unroll
    for (int i = 0; i < 4; i++)
      #pragma unroll
      for (int j = 0; j < 8; j++) sacc[i][j] = 0.f;

    const __half2* qp2 = qsh2 + tt;
    const __half2* kp2 = ksh + sp0;

    #pragma unroll
    for (int dc = 0; dc < 4; dc++) {
      __half2 sc2[4][4];
      #pragma unroll
      for (int i = 0; i < 4; i++)
        #pragma unroll
        for (int jp = 0; jp < 4; jp++) sc2[i][jp] = __float2half2_rn(0.f);

      #pragma unroll 4
      for (int dd = 0; dd < 16; dd++) {
        int d = dc*16 + dd;
        __half2 qq[4];  // 4 queries, pre-duplicated
        *(uint4*)qq = *(const uint4*)(qp2 + d*72);
        __half2 kk[4];  // 4 source pairs
        *(uint4*)kk = *(const uint4*)(kp2 + d*36);
        #pragma unroll
        for (int i = 0; i < 4; i++)
          #pragma unroll
          for (int jp = 0; jp < 4; jp++)
            sc2[i][jp] = __hadd2(sc2[i][jp], habs2_(__hsub2(qq[i], kk[jp])));
      }
      #pragma unroll
      for (int i = 0; i < 4; i++)
        #pragma unroll
        for (int jp = 0; jp < 4; jp++) {
          float2 f = __half22float2(sc2[i][jp]);
          sacc[i][2*jp+0] += f.x;
          sacc[i][2*jp+1] += f.y;
        }
    }

    // e = exp2(SCALE_LOG2E * sum), masked past T (overwrite sacc with e)
    #pragma unroll
    for (int i = 0; i < 4; i++)
      #pragma unroll
      for (int j = 0; j < 8; j++) {
        float e;
        asm("ex2.approx.f32 %0, %1;" : "=f"(e) : "f"(sacc[i][j] * SCALE_LOG2E));
        if (s0 + g8 + j >= TT) e = 0.f;
        sacc[i][j] = e;
      }

    // denom: per-thread partial over this thread's 8 sources, one ATOMS per query
    #pragma unroll
    for (int i = 0; i < 4; i++) {
      float ds = ((sacc[i][0] + sacc[i][1]) + (sacc[i][2] + sacc[i][3]))
               + ((sacc[i][4] + sacc[i][5]) + (sacc[i][6] + sacc[i][7]));
      atomicAdd(&denom[tt + i], ds);
    }

    // store p duplicated as half2, transposed [s][t]
    #pragma unroll
    for (int j = 0; j < 8; j++) {
      __half2 pv[4];
      pv[0] = __floats2half2_rn(sacc[0][j], sacc[0][j]);
      pv[1] = __floats2half2_rn(sacc[1][j], sacc[1][j]);
      pv[2] = __floats2half2_rn(sacc[2][j], sacc[2][j]);
      pv[3] = __floats2half2_rn(sacc[3][j], sacc[3][j]);
      *(uint4*)&ps2[(g8+j)*68 + tt] = *(uint4*)pv;
    }
    __syncthreads();

    // ---- AV: HFMA2, 32-s chunks drained to fp32 ----
    const __half2* pp2 = ps2 + tt;
    const __half2* vp2 = vsh + sp0;
    #pragma unroll
    for (int half_ = 0; half_ < 2; half_++) {
      __half2 oa2[4][4];
      #pragma unroll
      for (int i = 0; i < 4; i++)
        #pragma unroll
        for (int jp = 0; jp < 4; jp++) oa2[i][jp] = __float2half2_rn(0.f);

      #pragma unroll 4
      for (int ss = 0; ss < 32; ss++) {
        int s = half_*32 + ss;
        __half2 pb[4];  // 4 queries' p, duplicated
        *(uint4*)pb = *(const uint4*)(pp2 + s*68);
        __half2 vv[4];  // 4 dim-pairs of v[s]
        *(uint4*)vv = *(const uint4*)(vp2 + s*36);
        #pragma unroll
        for (int i = 0; i < 4; i++)
          #pragma unroll
          for (int jp = 0; jp < 4; jp++)
            oa2[i][jp] = __hfma2(pb[i], vv[jp], oa2[i][jp]);
      }
      #pragma unroll
      for (int i = 0; i < 4; i++)
        #pragma unroll
        for (int jp = 0; jp < 4; jp++) {
          float2 f = __half22float2(oa2[i][jp]);
          oacc[i][2*jp+0] += f.x;
          oacc[i][2*jp+1] += f.y;
        }
    }
    __syncthreads();
  }

  // normalize by (1 + sum p) and store per-head output
  float* hop = g_ho + (size_t)(b*NHH + h)*TT*DD;
  #pragma unroll
  for (int i = 0; i < 4; i++) {
    int trow = t0 + tt + i;
    if (trow < TT) {
      float inv = 1.f / (1.f + denom[tt + i]);
      float4 o1, o2;
      o1.x = oacc[i][0]*inv; o1.y = oacc[i][1]*inv;
      o1.z = oacc[i][2]*inv; o1.w = oacc[i][3]*inv;
      o2.x = oacc[i][4]*inv; o2.y = oacc[i][5]*inv;
      o2.z = oacc[i][6]*inv; o2.w = oacc[i][7]*inv;
      *(float4*)&hop[trow*DD + g8]     = o1;
      *(float4*)&hop[trow*DD + g8 + 4] = o2;
    }
  }
}

// ---------------------------------------------------------------------------
// K3: sum over heads, ReLU, y = Wf . r + bias, out = x + y.
// ---------------------------------------------------------------------------
__global__ __launch_bounds__(256) void out_kernel(
    const float* __restrict__ x, const float* __restrict__ wf,
    float* __restrict__ out) {
  __shared__ float r[4][64];
  __shared__ float wfs[64*65];
  const int tl = threadIdx.x >> 6;
  const int w  = threadIdx.x & 63;
  const int token = blockIdx.x*4 + tl;
  const int b = token / TT, t = token - b*TT;

  for (int i = threadIdx.x; i < 64*65; i += 256) wfs[i] = wf[i];

  float s = 0.f;
  #pragma unroll
  for (int h = 0; h < NHH; h++)
    s += g_ho[((size_t)(b*NHH + h)*TT + t)*DD + w];
  r[tl][w] = fmaxf(s, 0.f);
  __syncthreads();

  float acc = wfs[w*65 + 64];
  #pragma unroll 8
  for (int k = 0; k < 64; k++)
    acc += wfs[w*65 + k] * r[tl][k];

  out[(size_t)token*DD + w] = x[(size_t)token*DD + w] + acc;
}

// ---------------------------------------------------------------------------
extern "C" void kernel_launch(void* const* d_in, const int* in_sizes, int n_in,
                              void* d_out, int out_size) {
  const float* x  = (const float*)d_in[0];  // [8,1000,64]
  const float* wq = (const float*)d_in[1];  // [512,65]
  const float* wv = (const float*)d_in[2];  // [512,65]
  const float* wk = (const float*)d_in[3];  // [8,64]
  const float* wf = (const float*)d_in[4];  // [64,65]
  float* out = (float*)d_out;               // [8,1000,64]

  (void)in_sizes; (void)n_in; (void)out_size;

  cudaFuncSetAttribute(attn_kernel, cudaFuncAttributeMaxDynamicSharedMemorySize,
                       ATTN_SMEM);

  qv_kernel<<<dim3(8000/64, 512/64, 2), 256>>>(x, wq, wv);
  attn_kernel<<<dim3(16, NHH, BB), 128, ATTN_SMEM>>>(x, wk);
  out_kernel<<<8000/4, 256>>>(x, wf, out);
}